// round 14
// baseline (speedup 1.0000x reference)
#include <cuda_runtime.h>
#include <math.h>
#include <stdint.h>

#define NROWS 65536
#define DDIM  1024
#define SDIM  512
#define KSLOTS 64

__device__ float g_E[NROWS * SDIM];
__device__ float g_C[NROWS * SDIM];
__device__ float g_T[NROWS * DDIM];
__device__ float g_attn[NROWS * KSLOTS];
__device__ float g_gate[NROWS];
#define OFF_KP   0
#define OFF_V    32768
#define OFF_M1   65536
#define OFF_M2   131072
#define OFF_VWO  196608
#define OFF_AGG  262144
#define WS_TOTAL 327680
__device__ float g_ws[WS_TOTAL];

// ---------------- tf32 / fma helpers ----------------------------------------
__device__ __forceinline__ uint32_t f2tf(float x) {
    uint32_t t; asm("cvt.rna.tf32.f32 %0, %1;" : "=r"(t) : "f"(x)); return t;
}
__device__ __forceinline__ void st4tf(uint32_t* p, float4 v) {
    p[0] = f2tf(v.x); p[1] = f2tf(v.y); p[2] = f2tf(v.z); p[3] = f2tf(v.w);
}
__device__ __forceinline__ void splitf(float x, uint32_t& h, uint32_t& l) {
    h = f2tf(x); l = f2tf(x - __uint_as_float(h));
}
__device__ __forceinline__ void st4split(uint32_t* ph, uint32_t* pl, float4 v) {
    splitf(v.x, ph[0], pl[0]); splitf(v.y, ph[1], pl[1]);
    splitf(v.z, ph[2], pl[2]); splitf(v.w, ph[3], pl[3]);
}
__device__ __forceinline__ void mma_tf32(float* d, const uint32_t* a,
                                         const uint32_t* b) {
    asm volatile(
        "mma.sync.aligned.m16n8k8.row.col.f32.tf32.tf32.f32 "
        "{%0,%1,%2,%3}, {%4,%5,%6,%7}, {%8,%9}, {%0,%1,%2,%3};\n"
        : "+f"(d[0]), "+f"(d[1]), "+f"(d[2]), "+f"(d[3])
        : "r"(a[0]), "r"(a[1]), "r"(a[2]), "r"(a[3]), "r"(b[0]), "r"(b[1]));
}
// FMA-only e^x (no MUFU): |rel err| ~1e-6
__device__ __forceinline__ float fexp(float x) {
    float t = fminf(fmaxf(x * 1.4426950408889634f, -126.f), 126.f);
    float z = t + 12582912.f;
    int n = __float_as_int(z) - 0x4B400000;
    float f = t - (z - 12582912.f);
    float p = 1.3333558e-3f;
    p = fmaf(p, f, 9.6181291e-3f);
    p = fmaf(p, f, 5.5504109e-2f);
    p = fmaf(p, f, 2.4022651e-1f);
    p = fmaf(p, f, 6.9314718e-1f);
    p = fmaf(p, f, 1.0f);
    return __int_as_float(__float_as_int(p) + (n << 23));
}
// FMA-only 1/a for a>0
__device__ __forceinline__ float frcp(float a) {
    float y = __int_as_float(0x7EF311C3 - __float_as_int(a));
    y = y * (2.f - a * y);
    y = y * (2.f - a * y);
    y = y * (2.f - a * y);
    return y;
}
__device__ __forceinline__ float fma_sigmoid(float v) {
    return frcp(1.f + fexp(-v));
}
__device__ __forceinline__ float fma_tanh(float v) {
    return 1.f - 2.f * frcp(1.f + fexp(2.f * v));
}

// ====== fused E/C tf32 GEMM: E=sigmoid(h@We+be), C=tanh(h@Wc+bc) =============
// Per CTA: M=64 rows of h (shared A tile!), N=128 cols of both We and Wc.
__global__ __launch_bounds__(256)
void ec_tf32_kernel(const float* __restrict__ H,
                    const float* __restrict__ We,
                    const float* __restrict__ Wc,
                    const float* __restrict__ be,
                    const float* __restrict__ bc,
                    float* __restrict__ Eo,
                    float* __restrict__ Co)
{
    __shared__ uint32_t As[2][64][20];
    __shared__ uint32_t Bes[2][16][136];
    __shared__ uint32_t Bcs[2][16][136];
    const int tid = threadIdx.x;
    const int bx = blockIdx.x, by = blockIdx.y;
    const int lane = tid & 31, w = tid >> 5;
    const int wm = w & 1, wn = w >> 1;           // warp grid 2(M) x 4(N)
    const int g = lane >> 2, cc = lane & 3;

    const int ar = tid >> 2, ac = (tid & 3) << 2;   // A: 64 rows x 16 k
    const int br = tid >> 5, bcl = (tid & 31) << 2; // B: 16 k x 128 n

    const float* Ag  = H  + (size_t)(by * 64 + ar) * 1024 + ac;
    const float* Beg = We + (size_t)br * 512 + bx * 128 + bcl;
    const float* Bcg = Wc + (size_t)br * 512 + bx * 128 + bcl;

    float accE[2][4][4], accC[2][4][4];
    #pragma unroll
    for (int i = 0; i < 2; ++i)
        #pragma unroll
        for (int j = 0; j < 4; ++j)
            #pragma unroll
            for (int r = 0; r < 4; ++r) { accE[i][j][r] = 0.f; accC[i][j][r] = 0.f; }

    float4 av  = *(const float4*)Ag;
    float4 e0v = *(const float4*)Beg;
    float4 e1v = *(const float4*)(Beg + (size_t)8 * 512);
    float4 c0v = *(const float4*)Bcg;
    float4 c1v = *(const float4*)(Bcg + (size_t)8 * 512);
    st4tf(&As[0][ar][ac], av);
    st4tf(&Bes[0][br][bcl], e0v);
    st4tf(&Bes[0][br + 8][bcl], e1v);
    st4tf(&Bcs[0][br][bcl], c0v);
    st4tf(&Bcs[0][br + 8][bcl], c1v);
    __syncthreads();

    int buf = 0;
    for (int kt = 0; kt < 64; ++kt) {
        if (kt < 63) {
            av  = *(const float4*)(Ag + (kt + 1) * 16);
            e0v = *(const float4*)(Beg + (size_t)(kt + 1) * 16 * 512);
            e1v = *(const float4*)(Beg + (size_t)((kt + 1) * 16 + 8) * 512);
            c0v = *(const float4*)(Bcg + (size_t)(kt + 1) * 16 * 512);
            c1v = *(const float4*)(Bcg + (size_t)((kt + 1) * 16 + 8) * 512);
        }
        #pragma unroll
        for (int s = 0; s < 2; ++s) {
            const int kk = s * 8;
            uint32_t af[2][4];
            #pragma unroll
            for (int mt = 0; mt < 2; ++mt) {
                const int m = wm * 32 + mt * 16 + g;
                af[mt][0] = As[buf][m][kk + cc];
                af[mt][1] = As[buf][m + 8][kk + cc];
                af[mt][2] = As[buf][m][kk + cc + 4];
                af[mt][3] = As[buf][m + 8][kk + cc + 4];
            }
            #pragma unroll
            for (int nt = 0; nt < 4; ++nt) {
                const int n = wn * 32 + nt * 8 + g;
                uint32_t bE[2], bC[2];
                bE[0] = Bes[buf][kk + cc][n];
                bE[1] = Bes[buf][kk + cc + 4][n];
                bC[0] = Bcs[buf][kk + cc][n];
                bC[1] = Bcs[buf][kk + cc + 4][n];
                #pragma unroll
                for (int mt = 0; mt < 2; ++mt) {
                    mma_tf32(accE[mt][nt], af[mt], bE);
                    mma_tf32(accC[mt][nt], af[mt], bC);
                }
            }
        }
        if (kt < 63) {
            buf ^= 1;
            st4tf(&As[buf][ar][ac], av);
            st4tf(&Bes[buf][br][bcl], e0v);
            st4tf(&Bes[buf][br + 8][bcl], e1v);
            st4tf(&Bcs[buf][br][bcl], c0v);
            st4tf(&Bcs[buf][br + 8][bcl], c1v);
            __syncthreads();
        }
    }

    #pragma unroll
    for (int mt = 0; mt < 2; ++mt) {
        const int row = by * 64 + wm * 32 + mt * 16 + g;
        #pragma unroll
        for (int nt = 0; nt < 4; ++nt) {
            const int col = bx * 128 + wn * 32 + nt * 8 + 2 * cc;
            const float be0 = be[col], be1 = be[col + 1];
            const float bc0 = bc[col], bc1 = bc[col + 1];
            float2 pe0, pe1, pc0, pc1;
            pe0.x = fma_sigmoid(accE[mt][nt][0] + be0);
            pe0.y = fma_sigmoid(accE[mt][nt][1] + be1);
            pe1.x = fma_sigmoid(accE[mt][nt][2] + be0);
            pe1.y = fma_sigmoid(accE[mt][nt][3] + be1);
            pc0.x = fma_tanh(accC[mt][nt][0] + bc0);
            pc0.y = fma_tanh(accC[mt][nt][1] + bc1);
            pc1.x = fma_tanh(accC[mt][nt][2] + bc0);
            pc1.y = fma_tanh(accC[mt][nt][3] + bc1);
            *(float2*)&Eo[(size_t)row * 512 + col] = pe0;
            *(float2*)&Eo[(size_t)(row + 8) * 512 + col] = pe1;
            *(float2*)&Co[(size_t)row * 512 + col] = pc0;
            *(float2*)&Co[(size_t)(row + 8) * 512 + col] = pc1;
        }
    }
}

// ====== attn GEMM [128x64, K=1024] + register softmax (NT=1 tf32, NT=3 split)
template<int NT>
__global__ __launch_bounds__(256, 2)
void attn_kernel(const float* __restrict__ A, const float* __restrict__ Bm,
                 float* __restrict__ out, float scale,
                 const float* __restrict__ gate)
{
    __shared__ uint32_t Ah[128][20], Bh[16][72];
    __shared__ uint32_t Al[NT == 3 ? 128 : 1][20];
    __shared__ uint32_t Bl[NT == 3 ? 16 : 1][72];
    const int tid = threadIdx.x;
    const int lane = tid & 31, w = tid >> 5;
    const int g = lane >> 2, cc = lane & 3;
    const int m0 = w << 4;
    const int row0 = blockIdx.x * 128;

    const int ar = tid >> 1, ak = (tid & 1) << 3;
    const int br = tid >> 4, bn = (tid & 15) << 2;
    const float* Ag = A + (size_t)(row0 + ar) * 1024 + ak;
    const float* Bg = Bm + (size_t)br * 64 + bn;

    float acc[8][4];
    #pragma unroll
    for (int i = 0; i < 8; ++i)
        #pragma unroll
        for (int j = 0; j < 4; ++j) acc[i][j] = 0.f;

    float4 a0 = *(const float4*)Ag;
    float4 a1 = *(const float4*)(Ag + 4);
    float4 bv = *(const float4*)Bg;

    for (int kt = 0; kt < 64; ++kt) {
        if (NT == 3) {
            st4split(&Ah[ar][ak], &Al[ar][ak], a0);
            st4split(&Ah[ar][ak + 4], &Al[ar][ak + 4], a1);
            st4split(&Bh[br][bn], &Bl[br][bn], bv);
        } else {
            st4tf(&Ah[ar][ak], a0);
            st4tf(&Ah[ar][ak + 4], a1);
            st4tf(&Bh[br][bn], bv);
        }
        __syncthreads();
        if (kt < 63) {
            a0 = *(const float4*)(Ag + (kt + 1) * 16);
            a1 = *(const float4*)(Ag + (kt + 1) * 16 + 4);
            bv = *(const float4*)(Bg + (size_t)(kt + 1) * 16 * 64);
        }
        #pragma unroll
        for (int s = 0; s < 2; ++s) {
            const int kk = s * 8;
            uint32_t afh[4], afl[4];
            afh[0] = Ah[m0 + g][kk + cc];
            afh[1] = Ah[m0 + g + 8][kk + cc];
            afh[2] = Ah[m0 + g][kk + cc + 4];
            afh[3] = Ah[m0 + g + 8][kk + cc + 4];
            if (NT == 3) {
                afl[0] = Al[m0 + g][kk + cc];
                afl[1] = Al[m0 + g + 8][kk + cc];
                afl[2] = Al[m0 + g][kk + cc + 4];
                afl[3] = Al[m0 + g + 8][kk + cc + 4];
            }
            #pragma unroll
            for (int nt = 0; nt < 8; ++nt) {
                uint32_t bfh[2];
                bfh[0] = Bh[kk + cc][nt * 8 + g];
                bfh[1] = Bh[kk + cc + 4][nt * 8 + g];
                mma_tf32(acc[nt], afh, bfh);
                if (NT == 3) {
                    uint32_t bfl[2];
                    bfl[0] = Bl[kk + cc][nt * 8 + g];
                    bfl[1] = Bl[kk + cc + 4][nt * 8 + g];
                    mma_tf32(acc[nt], afl, bfh);
                    mma_tf32(acc[nt], afh, bfl);
                }
            }
        }
        __syncthreads();
    }

    float mx0 = -1e30f, mx1 = -1e30f;
    #pragma unroll
    for (int nt = 0; nt < 8; ++nt) {
        mx0 = fmaxf(mx0, fmaxf(acc[nt][0], acc[nt][1]));
        mx1 = fmaxf(mx1, fmaxf(acc[nt][2], acc[nt][3]));
    }
    #pragma unroll
    for (int s2 = 1; s2 <= 2; s2 <<= 1) {
        mx0 = fmaxf(mx0, __shfl_xor_sync(0xffffffffu, mx0, s2));
        mx1 = fmaxf(mx1, __shfl_xor_sync(0xffffffffu, mx1, s2));
    }
    mx0 *= scale; mx1 *= scale;
    float s0 = 0.f, s1 = 0.f;
    #pragma unroll
    for (int nt = 0; nt < 8; ++nt) {
        acc[nt][0] = fexp(acc[nt][0] * scale - mx0);
        acc[nt][1] = fexp(acc[nt][1] * scale - mx0);
        acc[nt][2] = fexp(acc[nt][2] * scale - mx1);
        acc[nt][3] = fexp(acc[nt][3] * scale - mx1);
        s0 += acc[nt][0] + acc[nt][1];
        s1 += acc[nt][2] + acc[nt][3];
    }
    #pragma unroll
    for (int s2 = 1; s2 <= 2; s2 <<= 1) {
        s0 += __shfl_xor_sync(0xffffffffu, s0, s2);
        s1 += __shfl_xor_sync(0xffffffffu, s1, s2);
    }
    const int ra = row0 + m0 + g;
    const float g0 = gate ? gate[ra] : 1.f;
    const float g1 = gate ? gate[ra + 8] : 1.f;
    const float f0 = g0 / s0, f1 = g1 / s1;
    #pragma unroll
    for (int nt = 0; nt < 8; ++nt) {
        const int col = nt * 8 + 2 * cc;
        float2 p0; p0.x = acc[nt][0] * f0; p0.y = acc[nt][1] * f0;
        float2 p1; p1.x = acc[nt][2] * f1; p1.y = acc[nt][3] * f1;
        *(float2*)&out[(size_t)ra * 64 + col] = p0;
        *(float2*)&out[(size_t)(ra + 8) * 64 + col] = p1;
    }
}

// ---------------- 128x128x8 SGEMM (K=64 read GEMM, +residual) ----------------
template<int OP>
__global__ __launch_bounds__(256, 2)
void sgemm128(const float* __restrict__ A, int lda,
              const float* __restrict__ B, int ldb,
              float* __restrict__ C, int ldc, int Kdim,
              const float* __restrict__ X)
{
    __shared__ float As[2][8][128];
    __shared__ float Bs[2][8][128];
    const int tid = threadIdx.x;
    const int bx = blockIdx.x, by = blockIdx.y;
    const int tr = (tid >> 4) << 3;
    const int tc = (tid & 15) << 3;
    const int aRow = tid >> 1, aCol = (tid & 1) << 2;
    const int bRow = tid >> 5, bCol = (tid & 31) << 2;

    const float* Aptr = A + (size_t)(by * 128 + aRow) * lda + aCol;
    const float* Bptr = B + (size_t)bRow * ldb + bx * 128 + bCol;

    float acc[8][8];
    #pragma unroll
    for (int i = 0; i < 8; ++i)
        #pragma unroll
        for (int j = 0; j < 8; ++j) acc[i][j] = 0.f;

    float4 av = *(const float4*)Aptr;
    float4 bv = *(const float4*)Bptr;
    As[0][aCol + 0][aRow] = av.x; As[0][aCol + 1][aRow] = av.y;
    As[0][aCol + 2][aRow] = av.z; As[0][aCol + 3][aRow] = av.w;
    *(float4*)&Bs[0][bRow][bCol] = bv;
    __syncthreads();

    const int KT = Kdim >> 3;
    int buf = 0;
    for (int kt = 0; kt < KT; ++kt) {
        if (kt + 1 < KT) {
            av = *(const float4*)(Aptr + (kt + 1) * 8);
            bv = *(const float4*)(Bptr + (size_t)(kt + 1) * 8 * ldb);
        }
        #pragma unroll
        for (int kk = 0; kk < 8; ++kk) {
            float a0[8], b0[8];
            *(float4*)&a0[0] = *(const float4*)&As[buf][kk][tr];
            *(float4*)&a0[4] = *(const float4*)&As[buf][kk][tr + 4];
            *(float4*)&b0[0] = *(const float4*)&Bs[buf][kk][tc];
            *(float4*)&b0[4] = *(const float4*)&Bs[buf][kk][tc + 4];
            #pragma unroll
            for (int i = 0; i < 8; ++i)
                #pragma unroll
                for (int j = 0; j < 8; ++j) acc[i][j] += a0[i] * b0[j];
        }
        if (kt + 1 < KT) {
            buf ^= 1;
            As[buf][aCol + 0][aRow] = av.x; As[buf][aCol + 1][aRow] = av.y;
            As[buf][aCol + 2][aRow] = av.z; As[buf][aCol + 3][aRow] = av.w;
            *(float4*)&Bs[buf][bRow][bCol] = bv;
            __syncthreads();
        }
    }
    const int row0 = by * 128 + tr;
    const int col0 = bx * 128 + tc;
    #pragma unroll
    for (int i = 0; i < 8; ++i) {
        size_t off = (size_t)(row0 + i) * ldc + col0;
        float outv[8];
        #pragma unroll
        for (int j = 0; j < 8; ++j) {
            float v = acc[i][j];
            if (OP == 1) v += X[off + j];
            outv[j] = v;
        }
        *(float4*)&C[off]     = *(float4*)&outv[0];
        *(float4*)&C[off + 4] = *(float4*)&outv[4];
    }
}

// -------- prologue small GEMMs (split-K x4, atomic) --------------------------
__global__ __launch_bounds__(256)
void state_proj_kernel(const float* __restrict__ state,
                       const float* __restrict__ Wk,
                       const float* __restrict__ Wv,
                       float* __restrict__ Kp, float* __restrict__ V)
{
    const float* B = (blockIdx.y == 0) ? Wk : Wv;
    float* C = (blockIdx.y == 0) ? Kp : V;
    const int bx = blockIdx.x, kz = blockIdx.z;
    __shared__ float As[16][64];
    __shared__ float Bs[16][64];
    const int tid = threadIdx.x;
    const int rb = (tid >> 4) << 2, cb = (tid & 15) << 2;
    float acc[4][4];
    #pragma unroll
    for (int i = 0; i < 4; ++i)
        #pragma unroll
        for (int j = 0; j < 4; ++j) acc[i][j] = 0.f;

    for (int kt = kz * 8; kt < kz * 8 + 8; ++kt) {
        const int k0 = kt * 16;
        {
            int r = tid >> 2, c4 = (tid & 3) << 2;
            float4 v = *(const float4*)&state[r * 512 + k0 + c4];
            As[c4 + 0][r] = v.x; As[c4 + 1][r] = v.y;
            As[c4 + 2][r] = v.z; As[c4 + 3][r] = v.w;
        }
        {
            int r = tid >> 4, c4 = (tid & 15) << 2;
            *(float4*)&Bs[r][c4] = *(const float4*)&B[(k0 + r) * 512 + bx * 64 + c4];
        }
        __syncthreads();
        #pragma unroll
        for (int kk = 0; kk < 16; ++kk) {
            float a[4], b[4];
            *(float4*)a = *(const float4*)&As[kk][rb];
            *(float4*)b = *(const float4*)&Bs[kk][cb];
            #pragma unroll
            for (int i = 0; i < 4; ++i)
                #pragma unroll
                for (int j = 0; j < 4; ++j) acc[i][j] += a[i] * b[j];
        }
        __syncthreads();
    }
    #pragma unroll
    for (int i = 0; i < 4; ++i)
        #pragma unroll
        for (int j = 0; j < 4; ++j)
            atomicAdd(&C[(rb + i) * 512 + bx * 64 + cb + j], acc[i][j]);
}

__global__ __launch_bounds__(256)
void abt_kernel(const float* __restrict__ A, const float* __restrict__ B,
                float* __restrict__ C)
{
    const int r0 = blockIdx.x * 64, kz = blockIdx.y;
    __shared__ float As[16][68];
    __shared__ float Bs[16][68];
    const int tid = threadIdx.x;
    const int rb = (tid >> 4) << 2, cb = (tid & 15) << 2;
    const int lr = tid >> 2, lc4 = (tid & 3) << 2;
    float acc[4][4];
    #pragma unroll
    for (int i = 0; i < 4; ++i)
        #pragma unroll
        for (int j = 0; j < 4; ++j) acc[i][j] = 0.f;

    for (int kt = kz * 8; kt < kz * 8 + 8; ++kt) {
        const int k0 = kt * 16;
        float4 va = *(const float4*)&A[(size_t)(r0 + lr) * 512 + k0 + lc4];
        float4 vb = *(const float4*)&B[(size_t)lr * 512 + k0 + lc4];
        As[lc4 + 0][lr] = va.x; As[lc4 + 1][lr] = va.y;
        As[lc4 + 2][lr] = va.z; As[lc4 + 3][lr] = va.w;
        Bs[lc4 + 0][lr] = vb.x; Bs[lc4 + 1][lr] = vb.y;
        Bs[lc4 + 2][lr] = vb.z; Bs[lc4 + 3][lr] = vb.w;
        __syncthreads();
        #pragma unroll
        for (int kk = 0; kk < 16; ++kk) {
            float a[4], b[4];
            *(float4*)a = *(const float4*)&As[kk][rb];
            *(float4*)b = *(const float4*)&Bs[kk][cb];
            #pragma unroll
            for (int i = 0; i < 4; ++i)
                #pragma unroll
                for (int j = 0; j < 4; ++j) acc[i][j] += a[i] * b[j];
        }
        __syncthreads();
    }
    #pragma unroll
    for (int i = 0; i < 4; ++i)
        #pragma unroll
        for (int j = 0; j < 4; ++j)
            atomicAdd(&C[(size_t)(r0 + rb + i) * 64 + cb + j], acc[i][j]);
}

__global__ __launch_bounds__(256)
void smallab_kernel(const float* __restrict__ A, const float* __restrict__ B,
                    float* __restrict__ C, int NC)
{
    const int n0 = blockIdx.x * 64, kz = blockIdx.y;
    __shared__ float As[16][68];
    __shared__ float Bs[16][68];
    const int tid = threadIdx.x;
    const int rb = (tid >> 4) << 2, cb = (tid & 15) << 2;
    const int lr = tid >> 2, lc4 = (tid & 3) << 2;
    const int br = tid >> 4, bc4 = (tid & 15) << 2;
    float acc[4][4];
    #pragma unroll
    for (int i = 0; i < 4; ++i)
        #pragma unroll
        for (int j = 0; j < 4; ++j) acc[i][j] = 0.f;

    for (int kt = kz * 8; kt < kz * 8 + 8; ++kt) {
        const int k0 = kt * 16;
        float4 va = *(const float4*)&A[(size_t)lr * 512 + k0 + lc4];
        As[lc4 + 0][lr] = va.x; As[lc4 + 1][lr] = va.y;
        As[lc4 + 2][lr] = va.z; As[lc4 + 3][lr] = va.w;
        *(float4*)&Bs[br][bc4] =
            *(const float4*)&B[(size_t)(k0 + br) * NC + n0 + bc4];
        __syncthreads();
        #pragma unroll
        for (int kk = 0; kk < 16; ++kk) {
            float a[4], b[4];
            *(float4*)a = *(const float4*)&As[kk][rb];
            *(float4*)b = *(const float4*)&Bs[kk][cb];
            #pragma unroll
            for (int i = 0; i < 4; ++i)
                #pragma unroll
                for (int j = 0; j < 4; ++j) acc[i][j] += a[i] * b[j];
        }
        __syncthreads();
    }
    #pragma unroll
    for (int i = 0; i < 4; ++i)
        #pragma unroll
        for (int j = 0; j < 4; ++j)
            atomicAdd(&C[(size_t)(rb + i) * NC + n0 + cb + j], acc[i][j]);
}

// ---------------- layernorm fused with write-gate dot ------------------------
__global__ __launch_bounds__(256)
void ln_gate_kernel(const float* __restrict__ T, const float* __restrict__ gamma,
                    const float* __restrict__ beta, const float* __restrict__ Wg,
                    const float* __restrict__ bgp, float* __restrict__ H,
                    float* __restrict__ gate)
{
    __shared__ float sm[8], sm2[8];
    __shared__ float s_mu, s_inv;
    const int row = blockIdx.x;
    const int t = threadIdx.x;
    const size_t base = (size_t)row * 1024 + t * 4;
    float4 v = *(const float4*)&T[base];
    float s  = v.x + v.y + v.z + v.w;
    float sq = v.x * v.x + v.y * v.y + v.z * v.z + v.w * v.w;
    #pragma unroll
    for (int o = 16; o > 0; o >>= 1) {
        s  += __shfl_down_sync(0xffffffffu, s, o);
        sq += __shfl_down_sync(0xffffffffu, sq, o);
    }
    const int lane = t & 31, w = t >> 5;
    if (lane == 0) { sm[w] = s; sm2[w] = sq; }
    __syncthreads();
    if (t == 0) {
        float S = 0.f, Q = 0.f;
        #pragma unroll
        for (int i = 0; i < 8; ++i) { S += sm[i]; Q += sm2[i]; }
        float mu = S * (1.f / 1024.f);
        float var = Q * (1.f / 1024.f) - mu * mu;
        s_mu = mu; s_inv = rsqrtf(var + 1e-6f);
    }
    __syncthreads();
    const float mu = s_mu, inv = s_inv;
    float4 g4 = *(const float4*)&gamma[t * 4];
    float4 b4 = *(const float4*)&beta[t * 4];
    float4 h;
    h.x = (v.x - mu) * inv * g4.x + b4.x;
    h.y = (v.y - mu) * inv * g4.y + b4.y;
    h.z = (v.z - mu) * inv * g4.z + b4.z;
    h.w = (v.w - mu) * inv * g4.w + b4.w;
    *(float4*)&H[base] = h;
    float4 wg = *(const float4*)&Wg[t * 4];
    float gd = h.x * wg.x + h.y * wg.y + h.z * wg.z + h.w * wg.w;
    #pragma unroll
    for (int o = 16; o > 0; o >>= 1) gd += __shfl_down_sync(0xffffffffu, gd, o);
    __syncthreads();
    if (lane == 0) sm[w] = gd;
    __syncthreads();
    if (t == 0) {
        float G = 0.f;
        #pragma unroll
        for (int i = 0; i < 8; ++i) G += sm[i];
        gate[row] = fma_sigmoid(G + bgp[0]);
    }
}

// ====== fused tf32 aggregation ===============================================
__global__ __launch_bounds__(256, 2)
void agg2_tf32_kernel(const float* __restrict__ Wt, const float* __restrict__ E,
                      const float* __restrict__ C, float* __restrict__ aggE,
                      float* __restrict__ aggC)
{
    __shared__ uint32_t As[64][20];
    __shared__ uint32_t Es[16][136];
    __shared__ uint32_t Cs[16][136];
    const int tid = threadIdx.x;
    const int lane = tid & 31, w = tid >> 5;
    const int g = lane >> 2, cc = lane & 3;
    const int wm = w & 1, wn = w >> 1;
    const int col0 = blockIdx.x * 128;
    const int r0 = blockIdx.y * 1024;
    const int wrow = tid & 15, wslot = (tid >> 4) << 2;
    const int er = tid >> 4, ec = (tid & 15) << 3;

    float accE[2][4][4], accC[2][4][4];
    #pragma unroll
    for (int i = 0; i < 2; ++i)
        #pragma unroll
        for (int j = 0; j < 4; ++j)
            #pragma unroll
            for (int r = 0; r < 4; ++r) { accE[i][j][r] = 0.f; accC[i][j][r] = 0.f; }

    for (int it = 0; it < 64; ++it) {
        const int rr = r0 + it * 16;
        float4 wv = *(const float4*)&Wt[(size_t)(rr + wrow) * 64 + wslot];
        As[wslot + 0][wrow] = f2tf(wv.x);
        As[wslot + 1][wrow] = f2tf(wv.y);
        As[wslot + 2][wrow] = f2tf(wv.z);
        As[wslot + 3][wrow] = f2tf(wv.w);
        const size_t eb = (size_t)(rr + er) * 512 + col0 + ec;
        float4 e0 = *(const float4*)&E[eb];
        float4 e1 = *(const float4*)&E[eb + 4];
        float4 c0 = *(const float4*)&C[eb];
        float4 c1 = *(const float4*)&C[eb + 4];
        st4tf(&Es[er][ec], e0); st4tf(&Es[er][ec + 4], e1);
        st4tf(&Cs[er][ec], c0); st4tf(&Cs[er][ec + 4], c1);
        __syncthreads();
        #pragma unroll
        for (int s = 0; s < 2; ++s) {
            const int kk = s * 8;
            uint32_t af[2][4];
            #pragma unroll
            for (int mt = 0; mt < 2; ++mt) {
                const int m = wm * 32 + mt * 16 + g;
                af[mt][0] = As[m][kk + cc];
                af[mt][1] = As[m + 8][kk + cc];
                af[mt][2] = As[m][kk + cc + 4];
                af[mt][3] = As[m + 8][kk + cc + 4];
            }
            #pragma unroll
            for (int nt = 0; nt < 4; ++nt) {
                const int n = wn * 32 + nt * 8 + g;
                uint32_t bE[2], bC[2];
                bE[0] = Es[kk + cc][n]; bE[1] = Es[kk + cc + 4][n];
                bC[0] = Cs[kk + cc][n]; bC[1] = Cs[kk + cc + 4][n];
                #pragma unroll
                for (int mt = 0; mt < 2; ++mt) {
                    mma_tf32(accE[mt][nt], af[mt], bE);
                    mma_tf32(accC[mt][nt], af[mt], bC);
                }
            }
        }
        __syncthreads();
    }
    #pragma unroll
    for (int mt = 0; mt < 2; ++mt) {
        const int slot = wm * 32 + mt * 16 + g;
        #pragma unroll
        for (int nt = 0; nt < 4; ++nt) {
            const int col = col0 + wn * 32 + nt * 8 + 2 * cc;
            atomicAdd(&aggE[slot * 512 + col],           accE[mt][nt][0]);
            atomicAdd(&aggE[slot * 512 + col + 1],       accE[mt][nt][1]);
            atomicAdd(&aggE[(slot + 8) * 512 + col],     accE[mt][nt][2]);
            atomicAdd(&aggE[(slot + 8) * 512 + col + 1], accE[mt][nt][3]);
            atomicAdd(&aggC[slot * 512 + col],           accC[mt][nt][0]);
            atomicAdd(&aggC[slot * 512 + col + 1],       accC[mt][nt][1]);
            atomicAdd(&aggC[(slot + 8) * 512 + col],     accC[mt][nt][2]);
            atomicAdd(&aggC[(slot + 8) * 512 + col + 1], accC[mt][nt][3]);
        }
    }
}

__global__ void zero_kernel(float* p, int n) {
    int i = blockIdx.x * blockDim.x + threadIdx.x;
    if (i < n) p[i] = 0.f;
}

__global__ void final_state_kernel(const float* __restrict__ state,
                                   const float* __restrict__ er,
                                   const float* __restrict__ wr,
                                   float* __restrict__ out)
{
    int i = blockIdx.x * blockDim.x + threadIdx.x;
    float e = fminf(fmaxf(er[i], 0.f), 1.f);
    out[i] = state[i] * (1.f - e) + wr[i];
}

// ------------------------------- launch --------------------------------------
extern "C" void kernel_launch(void* const* d_in, const int* in_sizes, int n_in,
                              void* d_out, int out_size)
{
    const float* X     = (const float*)d_in[0];
    const float* state = (const float*)d_in[1];
    const float* Wq    = (const float*)d_in[2];
    const float* Wk    = (const float*)d_in[3];
    const float* Wv    = (const float*)d_in[4];
    const float* Wo    = (const float*)d_in[5];
    const float* gamma = (const float*)d_in[6];
    const float* beta  = (const float*)d_in[7];
    const float* Wa    = (const float*)d_in[8];
    const float* Wg    = (const float*)d_in[9];
    const float* bg    = (const float*)d_in[10];
    const float* We    = (const float*)d_in[11];
    const float* be    = (const float*)d_in[12];
    const float* Wc    = (const float*)d_in[13];
    const float* bc    = (const float*)d_in[14];
    float* out = (float*)d_out;

    float *pE, *pC, *pT, *pAttn, *pGate, *pWS;
    cudaGetSymbolAddress((void**)&pE, g_E);
    cudaGetSymbolAddress((void**)&pC, g_C);
    cudaGetSymbolAddress((void**)&pT, g_T);
    cudaGetSymbolAddress((void**)&pAttn, g_attn);
    cudaGetSymbolAddress((void**)&pGate, g_gate);
    cudaGetSymbolAddress((void**)&pWS, g_ws);
    float* pKp  = pWS + OFF_KP;
    float* pV   = pWS + OFF_V;
    float* pM1  = pWS + OFF_M1;
    float* pM2  = pWS + OFF_M2;
    float* pVWo = pWS + OFF_VWO;
    float* pAgg0 = pWS + OFF_AGG;
    float* pAgg1 = pWS + OFF_AGG + KSLOTS * SDIM;

    const float scale = 1.0f / sqrtf((float)SDIM);

    zero_kernel<<<WS_TOTAL / 512, 512>>>(pWS, WS_TOTAL);

    state_proj_kernel<<<dim3(8, 2, 4), 256>>>(state, Wk, Wv, pKp, pV);
    abt_kernel<<<dim3(16, 4), 256>>>(Wq, pKp, pM1);
    abt_kernel<<<dim3(16, 4), 256>>>(Wa, state, pM2);
    smallab_kernel<<<dim3(16, 4), 256>>>(pV, Wo, pVWo, DDIM);

    // attn = softmax(X @ M1 * scale)
    attn_kernel<1><<<512, 256>>>(X, pM1, pAttn, scale, nullptr);
    // T = X + attn @ VWo
    sgemm128<1><<<dim3(8, 512), 256>>>(pAttn, KSLOTS, pVWo, DDIM, pT, DDIM,
                                       KSLOTS, X);
    // h = LN(T) -> out; gate = sigmoid(h.Wg + bg)
    ln_gate_kernel<<<NROWS, 256>>>(pT, gamma, beta, Wg, bg, out, pGate);
    // weighted = gate * softmax(h @ M2)  (split-tf32, fp32-accurate)
    attn_kernel<3><<<512, 256>>>(out, pM2, pAttn, 1.0f, pGate);
    // E = sigmoid(h@We+be), C = tanh(h@Wc+bc)  -- fused tf32, shared A tile
    ec_tf32_kernel<<<dim3(4, 1024), 256>>>(out, We, Wc, be, bc, pE, pC);
    // aggregations
    agg2_tf32_kernel<<<dim3(4, 64), 256>>>(pAttn, pE, pC, pAgg0, pAgg1);
    // new_state
    final_state_kernel<<<64, 512>>>(state, pAgg0, pAgg1,
                                    out + (size_t)NROWS * DDIM);
}